// round 2
// baseline (speedup 1.0000x reference)
#include <cuda_runtime.h>

#define NOISE   128
#define OUTF    512
#define XCOLS   640        // 128 noise + 512 feats
#define WCOLS   262656     // 512*512 + 512
#define WB_OFF  262144

#define KB          16
#define CHUNKS_TOTAL 4137  // 4096 (main) + 32 (feat-bias) + 8 (noise-bias) + 1 (const bias)
#define SPLITS      18
#define CH_PER      ((CHUNKS_TOTAL + SPLITS - 1) / SPLITS)   // 230

#define MB 128
#define NB 64
#define AS_STRIDE 130      // 128 + 2 pad: conflict-free STS/LDS, keeps 8B alignment

__device__ __forceinline__ void fma2(unsigned long long& d, unsigned long long a, unsigned long long b) {
    asm("fma.rn.f32x2 %0, %1, %2, %3;" : "=l"(d) : "l"(a), "l"(b), "l"(d));
}
__device__ __forceinline__ unsigned long long pack2(float x) {
    unsigned long long r;
    asm("mov.b64 %0, {%1, %1};" : "=l"(r) : "f"(x));
    return r;
}
__device__ __forceinline__ void unpack2(unsigned long long v, float& lo, float& hi) {
    asm("mov.b64 {%0, %1}, %2;" : "=f"(lo), "=f"(hi) : "l"(v));
}

__global__ void zero_out_kernel(float* out) {
    int i = blockIdx.x * blockDim.x + threadIdx.x;
    float4 z = make_float4(0.f, 0.f, 0.f, 0.f);
    reinterpret_cast<float4*>(out)[i] = z;
}

__global__ __launch_bounds__(256, 2)
void hyper_main(const float* __restrict__ x, const float* __restrict__ W,
                const float* __restrict__ bv, float* __restrict__ out)
{
    __shared__ float As[2][KB][AS_STRIDE];
    __shared__ float Bs[2][KB][NB];

    const int m0 = blockIdx.x * MB;          // batch tile (2 tiles)
    const int n0 = blockIdx.y * NB;          // output tile (8 tiles)
    const int s  = blockIdx.z;               // K-split
    const int c0 = s * CH_PER;
    const int c1 = min(CHUNKS_TOTAL, c0 + CH_PER);

    const int tid = threadIdx.x;
    // A-staging role: thread -> (local batch, half of the 16 kk's)
    const int sb = tid >> 1;                 // 0..127
    const int sp = tid & 1;                  // 0..1
    // B-staging role: thread -> (kk row, float4 within 64-wide row)
    const int skk = tid >> 4;                // 0..15
    const int sf  = tid & 15;                // 0..15
    // compute role
    const int tx = tid & 15;                 // o-group: o = n0 + tx*4 + q
    const int ty = tid >> 4;                 // b-group: b = m0 + ty*8 + ...

    const float* xr = x + (long)(m0 + sb) * XCOLS;

    unsigned long long acc[4][4];
    #pragma unroll
    for (int i = 0; i < 4; i++)
        #pragma unroll
        for (int j = 0; j < 4; j++) acc[i][j] = 0ull;

    // ---- prefetch registers (live across compute to overlap LDG latency) ----
    float4 fa0, fa1, fb;
    float  nv = 0.f;
    int    caseid = 0;

    auto prefetch = [&](int c) {
        if (c < 4096) {                      // main term: noise[b,k]*feats[b,i] * W[k, i*512+o]
            caseid = 0;
            int k  = c >> 5;
            int i0 = (c & 31) << 4;
            nv  = xr[k];
            fa0 = *reinterpret_cast<const float4*>(xr + NOISE + i0 + sp * 8);
            fa1 = *reinterpret_cast<const float4*>(xr + NOISE + i0 + sp * 8 + 4);
            const float* wp = W + (long)k * WCOLS + (long)(i0 + skk) * OUTF + n0;
            fb = *reinterpret_cast<const float4*>(wp + sf * 4);
        } else if (c < 4128) {               // feats @ bias-weight
            caseid = 1;
            int i0 = (c - 4096) << 4;
            fa0 = *reinterpret_cast<const float4*>(xr + NOISE + i0 + sp * 8);
            fa1 = *reinterpret_cast<const float4*>(xr + NOISE + i0 + sp * 8 + 4);
            const float* bp = bv + (long)(i0 + skk) * OUTF + n0;
            fb = *reinterpret_cast<const float4*>(bp + sf * 4);
        } else if (c < 4136) {               // noise @ W_bias
            caseid = 2;
            int k0 = (c - 4128) << 4;
            fa0 = *reinterpret_cast<const float4*>(xr + k0 + sp * 8);
            fa1 = *reinterpret_cast<const float4*>(xr + k0 + sp * 8 + 4);
            const float* wp = W + (long)(k0 + skk) * WCOLS + WB_OFF + n0;
            fb = *reinterpret_cast<const float4*>(wp + sf * 4);
        } else {                             // constant bias row (A = 1 for kk==0 only)
            caseid = 3;
            const float* bp = bv + WB_OFF + n0;
            fb = *reinterpret_cast<const float4*>(bp + sf * 4);
        }
    };

    auto store_stage = [&](int buf) {
        float a[8];
        if (caseid == 0) {
            a[0] = nv * fa0.x; a[1] = nv * fa0.y; a[2] = nv * fa0.z; a[3] = nv * fa0.w;
            a[4] = nv * fa1.x; a[5] = nv * fa1.y; a[6] = nv * fa1.z; a[7] = nv * fa1.w;
        } else if (caseid == 3) {
            #pragma unroll
            for (int j = 0; j < 8; j++) a[j] = 0.f;
            if (sp == 0) a[0] = 1.f;
        } else {
            a[0] = fa0.x; a[1] = fa0.y; a[2] = fa0.z; a[3] = fa0.w;
            a[4] = fa1.x; a[5] = fa1.y; a[6] = fa1.z; a[7] = fa1.w;
        }
        #pragma unroll
        for (int j = 0; j < 8; j++) As[buf][sp * 8 + j][sb] = a[j];
        *reinterpret_cast<float4*>(&Bs[buf][skk][sf * 4]) = fb;
    };

    auto compute = [&](int buf) {
        #pragma unroll
        for (int kk = 0; kk < KB; kk++) {
            const unsigned long long* ap =
                reinterpret_cast<const unsigned long long*>(&As[buf][kk][ty * 8]);
            unsigned long long a2[4];
            #pragma unroll
            for (int bp = 0; bp < 4; bp++) a2[bp] = ap[bp];
            float4 w = *reinterpret_cast<const float4*>(&Bs[buf][kk][tx * 4]);
            unsigned long long w2[4];
            w2[0] = pack2(w.x); w2[1] = pack2(w.y); w2[2] = pack2(w.z); w2[3] = pack2(w.w);
            #pragma unroll
            for (int bp = 0; bp < 4; bp++)
                #pragma unroll
                for (int q = 0; q < 4; q++)
                    fma2(acc[bp][q], a2[bp], w2[q]);
        }
    };

    const int nCh = c1 - c0;
    prefetch(c0);
    store_stage(0);
    for (int j = 0; j < nCh; j++) {
        __syncthreads();
        const int buf = j & 1;
        if (j + 1 < nCh) prefetch(c0 + j + 1);   // LDG in flight during compute
        compute(buf);
        if (j + 1 < nCh) store_stage(buf ^ 1);   // write OTHER buffer; sync guards reuse
    }

    // ---- epilogue: merge K-splits via reduction atomics ----
    #pragma unroll
    for (int bp = 0; bp < 4; bp++) {
        int b = m0 + ty * 8 + bp * 2;
        #pragma unroll
        for (int q = 0; q < 4; q++) {
            float lo, hi;
            unpack2(acc[bp][q], lo, hi);
            int o = n0 + tx * 4 + q;
            atomicAdd(&out[(long)b * OUTF + o], lo);
            atomicAdd(&out[(long)(b + 1) * OUTF + o], hi);
        }
    }
}

extern "C" void kernel_launch(void* const* d_in, const int* in_sizes, int n_in,
                              void* d_out, int out_size) {
    const float* x  = (const float*)d_in[0];   // (256, 640)
    const float* W  = (const float*)d_in[1];   // (128, 262656)
    const float* bv = (const float*)d_in[2];   // (262656,)
    float* out = (float*)d_out;                // (256, 512)

    zero_out_kernel<<<128, 256>>>(out);        // 32768 float4 = 131072 floats
    dim3 grid(2, 8, SPLITS);
    hyper_main<<<grid, 256>>>(x, W, bv, out);
}

// round 4
// speedup vs baseline: 8.8954x; 8.8954x over previous
#include <cuda_runtime.h>
#include <cstdint>

// ---------------- arch-feature detection ----------------
// Arch-specific (sm_103a/sm_100a) device pass -> tensor path.
// Family/base pass (compute_103 etc.) -> SIMT fallback path.
#if defined(__CUDA_ARCH__) && (defined(__CUDA_ARCH_FEAT_SM103_ALL) || defined(__CUDA_ARCH_FEAT_SM100_ALL) || defined(__CUDA_ARCH_SPECIFIC__))
#define HAS_TC 1
#else
#define HAS_TC 0
#endif

#define NOISE   128
#define OUTF    512
#define XCOLS   640
#define WCOLS   262656
#define WB_OFF  262144

// ======== tensor-path config ========
#define CHUNKS  2069       // 2048 main + 16 feat-bias + 4 noise-bias + 1 const
#define SPLITS  74
#define CHPER   28         // ceil(2069/74)
#define NST     3

#define SM_A(st, mt) (1024u + ((st)*2u + (mt))*16384u)    // 6 x 16KB A tiles
#define SM_B(st)     (99328u + (st)*32768u)               // 3 x 32KB B tiles
#define SMEM_TOTAL   197632
#define SM_MBAR(st)  (8u + (st)*8u)

// idesc: dtype F32(1)@[4], atype TF32(2)@[7:9], btype TF32(2)@[10:12], N=256 -> 32@[17:22], M=128 -> 8@[24:28]
#define IDESC_TF32 ((1u<<4)|(2u<<7)|(2u<<10)|(32u<<17)|(8u<<24))

__device__ float g_scratch[(size_t)SPLITS * 256 * 512];   // split partials (38.8MB)

// ======== SIMT fallback config ========
#define KB          16
#define FCHUNKS     4137
#define FSPLITS     18
#define FCHPER      ((FCHUNKS + FSPLITS - 1) / FSPLITS)
#define MB 128
#define NB 64
#define AS_STRIDE 130

// ---------------- common helpers ----------------
__device__ __forceinline__ void fma2(unsigned long long& d, unsigned long long a, unsigned long long b) {
    asm("fma.rn.f32x2 %0, %1, %2, %3;" : "=l"(d) : "l"(a), "l"(b), "l"(d));
}
__device__ __forceinline__ unsigned long long pack2(float x) {
    unsigned long long r;
    asm("mov.b64 %0, {%1, %1};" : "=l"(r) : "f"(x));
    return r;
}
__device__ __forceinline__ void unpack2(unsigned long long v, float& lo, float& hi) {
    asm("mov.b64 {%0, %1}, %2;" : "=f"(lo), "=f"(hi) : "l"(v));
}

__global__ void zero_out_kernel(float* out) {
    int i = blockIdx.x * blockDim.x + threadIdx.x;
    reinterpret_cast<float4*>(out)[i] = make_float4(0.f, 0.f, 0.f, 0.f);
}

// =====================================================================
// SIMT fallback GEMM (compiled only when tcgen05 arch features absent)
// =====================================================================
__global__ __launch_bounds__(256, 2)
void hyper_main(const float* __restrict__ x, const float* __restrict__ W,
                const float* __restrict__ bv, float* __restrict__ out)
{
#if !HAS_TC
    __shared__ float As[2][KB][AS_STRIDE];
    __shared__ float Bs[2][KB][NB];

    const int m0 = blockIdx.x * MB;
    const int n0 = blockIdx.y * NB;
    const int s  = blockIdx.z;
    const int c0 = s * FCHPER;
    const int c1 = min(FCHUNKS, c0 + FCHPER);

    const int tid = threadIdx.x;
    const int sb = tid >> 1, sp = tid & 1;
    const int skk = tid >> 4, sf = tid & 15;
    const int tx = tid & 15, ty = tid >> 4;

    const float* xr = x + (long)(m0 + sb) * XCOLS;

    unsigned long long acc[4][4];
    #pragma unroll
    for (int i = 0; i < 4; i++)
        #pragma unroll
        for (int j = 0; j < 4; j++) acc[i][j] = 0ull;

    float4 fa0, fa1, fb;
    float  nv = 0.f;
    int    caseid = 0;

    auto prefetch = [&](int c) {
        if (c < 4096) {
            caseid = 0;
            int k = c >> 5, i0 = (c & 31) << 4;
            nv  = xr[k];
            fa0 = *reinterpret_cast<const float4*>(xr + NOISE + i0 + sp * 8);
            fa1 = *reinterpret_cast<const float4*>(xr + NOISE + i0 + sp * 8 + 4);
            fb = *reinterpret_cast<const float4*>(W + (long)k * WCOLS + (long)(i0 + skk) * OUTF + n0 + sf * 4);
        } else if (c < 4128) {
            caseid = 1;
            int i0 = (c - 4096) << 4;
            fa0 = *reinterpret_cast<const float4*>(xr + NOISE + i0 + sp * 8);
            fa1 = *reinterpret_cast<const float4*>(xr + NOISE + i0 + sp * 8 + 4);
            fb = *reinterpret_cast<const float4*>(bv + (long)(i0 + skk) * OUTF + n0 + sf * 4);
        } else if (c < 4136) {
            caseid = 2;
            int k0 = (c - 4128) << 4;
            fa0 = *reinterpret_cast<const float4*>(xr + k0 + sp * 8);
            fa1 = *reinterpret_cast<const float4*>(xr + k0 + sp * 8 + 4);
            fb = *reinterpret_cast<const float4*>(W + (long)(k0 + skk) * WCOLS + WB_OFF + n0 + sf * 4);
        } else {
            caseid = 3;
            fb = *reinterpret_cast<const float4*>(bv + WB_OFF + n0 + sf * 4);
        }
    };

    auto store_stage = [&](int buf) {
        float a[8];
        if (caseid == 0) {
            a[0]=nv*fa0.x; a[1]=nv*fa0.y; a[2]=nv*fa0.z; a[3]=nv*fa0.w;
            a[4]=nv*fa1.x; a[5]=nv*fa1.y; a[6]=nv*fa1.z; a[7]=nv*fa1.w;
        } else if (caseid == 3) {
            #pragma unroll
            for (int j = 0; j < 8; j++) a[j] = 0.f;
            if (sp == 0) a[0] = 1.f;
        } else {
            a[0]=fa0.x; a[1]=fa0.y; a[2]=fa0.z; a[3]=fa0.w;
            a[4]=fa1.x; a[5]=fa1.y; a[6]=fa1.z; a[7]=fa1.w;
        }
        #pragma unroll
        for (int j = 0; j < 8; j++) As[buf][sp * 8 + j][sb] = a[j];
        *reinterpret_cast<float4*>(&Bs[buf][skk][sf * 4]) = fb;
    };

    auto compute = [&](int buf) {
        #pragma unroll
        for (int kk = 0; kk < KB; kk++) {
            const unsigned long long* ap =
                reinterpret_cast<const unsigned long long*>(&As[buf][kk][ty * 8]);
            unsigned long long a2[4];
            #pragma unroll
            for (int bp = 0; bp < 4; bp++) a2[bp] = ap[bp];
            float4 w = *reinterpret_cast<const float4*>(&Bs[buf][kk][tx * 4]);
            unsigned long long w2[4];
            w2[0]=pack2(w.x); w2[1]=pack2(w.y); w2[2]=pack2(w.z); w2[3]=pack2(w.w);
            #pragma unroll
            for (int bp = 0; bp < 4; bp++)
                #pragma unroll
                for (int q = 0; q < 4; q++)
                    fma2(acc[bp][q], a2[bp], w2[q]);
        }
    };

    const int nCh = c1 - c0;
    prefetch(c0);
    store_stage(0);
    for (int j = 0; j < nCh; j++) {
        __syncthreads();
        const int buf = j & 1;
        if (j + 1 < nCh) prefetch(c0 + j + 1);
        compute(buf);
        if (j + 1 < nCh) store_stage(buf ^ 1);
    }

    #pragma unroll
    for (int bp = 0; bp < 4; bp++) {
        int b = m0 + ty * 8 + bp * 2;
        #pragma unroll
        for (int q = 0; q < 4; q++) {
            float lo, hi;
            unpack2(acc[bp][q], lo, hi);
            int o = n0 + tx * 4 + q;
            atomicAdd(&out[(long)b * OUTF + o], lo);
            atomicAdd(&out[(long)(b + 1) * OUTF + o], hi);
        }
    }
#endif // !HAS_TC
}

// =====================================================================
// Tensor-core path (sm_103a-specific pass only)
// =====================================================================
#if HAS_TC
__device__ __forceinline__ uint32_t smem_u32(const void* p){
    uint32_t a;
    asm("{ .reg .u64 t; cvta.to.shared.u64 t, %1; cvt.u32.u64 %0, t; }" : "=r"(a) : "l"(p));
    return a;
}
__device__ __forceinline__ uint32_t sw128(uint32_t o){ return o ^ ((o >> 3) & 0x70u); }
__device__ __forceinline__ uint32_t f2tf32(float f){
    uint32_t r; asm("cvt.rna.tf32.f32 %0, %1;" : "=r"(r) : "f"(f)); return r;
}
__device__ __forceinline__ void sts128(uint32_t addr, uint32_t a, uint32_t b, uint32_t c, uint32_t d){
    asm volatile("st.shared.v4.b32 [%0], {%1,%2,%3,%4};"
                 :: "r"(addr), "r"(a), "r"(b), "r"(c), "r"(d) : "memory");
}
__device__ __forceinline__ bool elect1(){
    uint32_t p;
    asm volatile("{\n\t.reg .pred P;\n\telect.sync _|P, 0xFFFFFFFF;\n\tselp.b32 %0, 1, 0, P;\n\t}" : "=r"(p));
    return p != 0;
}
static constexpr unsigned long long DESC_BASE_SW128 =
    (2ull << 61) | (1ull << 46) | (64ull << 32) | (1ull << 16);
__device__ __forceinline__ uint64_t mkdesc(uint32_t addr){
    return DESC_BASE_SW128 | (uint64_t)((addr >> 4) & 0x3FFFu);
}
__device__ __forceinline__ void mma_tf32(uint32_t d, uint64_t ad, uint64_t bd, uint32_t en){
    asm volatile(
        "{\n\t.reg .pred p;\n\tsetp.ne.u32 p, %4, 0;\n\t"
        "tcgen05.mma.cta_group::1.kind::tf32 [%0], %1, %2, %3, {%5,%5,%5,%5}, p;\n\t}"
        :: "r"(d), "l"(ad), "l"(bd), "r"(IDESC_TF32), "r"(en), "r"(0u) : "memory");
}
#define TMEM_ALLOC(smem_addr, ncols) \
    asm volatile("tcgen05.alloc.cta_group::1.sync.aligned.shared::cta.b32 [%0], %1;" \
                 :: "r"(smem_addr), "r"((uint32_t)(ncols)) : "memory")
#define TMEM_DEALLOC(tmem, ncols) \
    asm volatile("tcgen05.dealloc.cta_group::1.sync.aligned.b32 %0, %1;" :: "r"(tmem), "r"((uint32_t)(ncols)))
#define TMEM_RELINQ() asm volatile("tcgen05.relinquish_alloc_permit.cta_group::1.sync.aligned;")
#define MBAR_INIT(a, n) \
    asm volatile("mbarrier.init.shared.b64 [%0], %1;" :: "r"(a), "r"((uint32_t)(n)) : "memory")
#define TC_COMMIT(a) \
    asm volatile("tcgen05.commit.cta_group::1.mbarrier::arrive::one.shared::cluster.b64 [%0];" :: "r"(a) : "memory")
#define FENCE_ASYNC() asm volatile("fence.proxy.async.shared::cta;" ::: "memory")
#define TC_FENCE_AFTER() asm volatile("tcgen05.fence::after_thread_sync;" ::: "memory")
#define TC_WAIT_LD() asm volatile("tcgen05.wait::ld.sync.aligned;" ::: "memory")

__device__ __forceinline__ void mbar_wait(uint32_t mbar, uint32_t parity){
    uint32_t done;
    asm volatile(
        "{\n\t.reg .pred p;\n\t"
        "mbarrier.try_wait.parity.acquire.cta.shared::cta.b64 p, [%1], %2;\n\t"
        "selp.b32 %0, 1, 0, p;\n\t}"
        : "=r"(done) : "r"(mbar), "r"(parity) : "memory");
    if (!done) {
        asm volatile(
            "{\n\t.reg .pred P1;\n\t"
            "WL_%=:\n\t"
            "mbarrier.try_wait.parity.acquire.cta.shared::cta.b64 P1, [%0], %1, 0x989680;\n\t"
            "@P1 bra.uni WD_%=;\n\t"
            "bra.uni WL_%=;\n\t"
            "WD_%=:\n\t}"
            :: "r"(mbar), "r"(parity) : "memory");
    }
}
#define LDTM_X32(r, a) \
    asm volatile("tcgen05.ld.sync.aligned.32x32b.x32.b32 " \
        "{%0,%1,%2,%3,%4,%5,%6,%7,%8,%9,%10,%11,%12,%13,%14,%15," \
        "%16,%17,%18,%19,%20,%21,%22,%23,%24,%25,%26,%27,%28,%29,%30,%31}, [%32];" \
        : "=r"((r)[0]),"=r"((r)[1]),"=r"((r)[2]),"=r"((r)[3]),"=r"((r)[4]),"=r"((r)[5]),"=r"((r)[6]),"=r"((r)[7]), \
          "=r"((r)[8]),"=r"((r)[9]),"=r"((r)[10]),"=r"((r)[11]),"=r"((r)[12]),"=r"((r)[13]),"=r"((r)[14]),"=r"((r)[15]), \
          "=r"((r)[16]),"=r"((r)[17]),"=r"((r)[18]),"=r"((r)[19]),"=r"((r)[20]),"=r"((r)[21]),"=r"((r)[22]),"=r"((r)[23]), \
          "=r"((r)[24]),"=r"((r)[25]),"=r"((r)[26]),"=r"((r)[27]),"=r"((r)[28]),"=r"((r)[29]),"=r"((r)[30]),"=r"((r)[31]) \
        : "r"(a))
#endif // HAS_TC

__global__ __launch_bounds__(256, 1)
void hyper_tc(const float* __restrict__ x, const float* __restrict__ W,
              const float* __restrict__ bv)
{
#if HAS_TC
    extern __shared__ char smem[];
    const uint32_t sb  = smem_u32(smem);
    const int tid = threadIdx.x;
    const int wid = tid >> 5;
    const int lid = tid & 31;
    const int nt  = blockIdx.x;
    const int s   = blockIdx.y;
    const int n0  = nt * 256;
    const int c0  = s * CHPER;
    const int c1  = min(CHUNKS, c0 + CHPER);
    const int nCh = c1 - c0;

    if (wid == 0) TMEM_ALLOC(sb, 512);
    if (tid == 0) { MBAR_INIT(sb + SM_MBAR(0), 1); MBAR_INIT(sb + SM_MBAR(1), 1); MBAR_INIT(sb + SM_MBAR(2), 1); }
    __syncthreads();
    uint32_t tb;
    asm volatile("ld.shared.b32 %0, [%1];" : "=r"(tb) : "r"(sb));

    const int m  = tid >> 1;
    const int h  = tid & 1;
    const int kk0 = h * 16;
    const float* xr0 = x + (long)m * XCOLS;
    const float* xr1 = x + (long)(128 + m) * XCOLS;

    float  br[32];
    float4 fa0[4], fa1[4];
    float  nv0 = 0.f, nv1 = 0.f;
    bool   is3 = false;

    auto prefetch = [&](int c){
        const float* bp; long bstr;
        const float* a0p = xr0; const float* a1p = xr1;
        is3 = false;
        if (c < 2048) {
            int k = c >> 4, i0 = (c & 15) << 5;
            bp = W + (long)k * WCOLS + (long)i0 * OUTF + n0 + tid; bstr = OUTF;
            nv0 = xr0[k]; nv1 = xr1[k];
            a0p = xr0 + NOISE + i0 + kk0; a1p = xr1 + NOISE + i0 + kk0;
        } else if (c < 2064) {
            int i0 = (c - 2048) << 5;
            bp = bv + (long)i0 * OUTF + n0 + tid; bstr = OUTF;
            nv0 = 1.f; nv1 = 1.f;
            a0p = xr0 + NOISE + i0 + kk0; a1p = xr1 + NOISE + i0 + kk0;
        } else if (c < 2068) {
            int k0 = (c - 2064) << 5;
            bp = W + (long)k0 * WCOLS + WB_OFF + n0 + tid; bstr = WCOLS;
            nv0 = 1.f; nv1 = 1.f;
            a0p = xr0 + k0 + kk0; a1p = xr1 + k0 + kk0;
        } else {
            bp = bv + WB_OFF + n0 + tid; bstr = 0;
            nv0 = 0.f; nv1 = 0.f; is3 = true;
        }
        #pragma unroll
        for (int kk = 0; kk < 32; kk++) br[kk] = bp[(long)kk * bstr];
        #pragma unroll
        for (int q = 0; q < 4; q++) {
            fa0[q] = *reinterpret_cast<const float4*>(a0p + q * 4);
            fa1[q] = *reinterpret_cast<const float4*>(a1p + q * 4);
        }
    };

    auto stage = [&](int st){
        uint32_t bb = sb + SM_B(st);
        #pragma unroll
        for (int q = 0; q < 8; q++) {
            uint32_t off = (uint32_t)tid * 128u + q * 16u;
            sts128(bb + sw128(off),
                   f2tf32(br[q*4+0]), f2tf32(br[q*4+1]), f2tf32(br[q*4+2]), f2tf32(br[q*4+3]));
        }
        #pragma unroll
        for (int mt = 0; mt < 2; mt++) {
            uint32_t ab = sb + SM_A(st, mt);
            float nv = mt ? nv1 : nv0;
            #pragma unroll
            for (int q = 0; q < 4; q++) {
                float4 f = mt ? fa1[q] : fa0[q];
                float v0 = nv * f.x, v1 = nv * f.y, v2 = nv * f.z, v3 = nv * f.w;
                if (is3 && h == 0 && q == 0) v0 = 1.f;
                uint32_t off = (uint32_t)m * 128u + (uint32_t)(kk0 + q * 4) * 4u;
                sts128(ab + sw128(off), f2tf32(v0), f2tf32(v1), f2tf32(v2), f2tf32(v3));
            }
        }
    };

    prefetch(c0);
    for (int j = 0; j < nCh; j++) {
        const int st = j % NST;
        if (j >= NST) mbar_wait(sb + SM_MBAR(st), (uint32_t)(((j / NST) - 1) & 1));
        stage(st);
        FENCE_ASYNC();
        if (j + 1 < nCh) prefetch(c0 + j + 1);
        __syncthreads();
        if (wid == 0) {
            if (elect1()) {
                uint64_t ad0 = mkdesc(sb + SM_A(st, 0));
                uint64_t ad1 = mkdesc(sb + SM_A(st, 1));
                uint64_t bd  = mkdesc(sb + SM_B(st));
                #pragma unroll
                for (int ks = 0; ks < 4; ks++) {
                    uint32_t en = (j == 0 && ks == 0) ? 0u : 1u;
                    mma_tf32(tb,        ad0 + ks * 2, bd + ks * 2, en);
                    mma_tf32(tb + 256u, ad1 + ks * 2, bd + ks * 2, en);
                }
                TC_COMMIT(sb + SM_MBAR(st));
            }
        }
    }

    const int jl = nCh - 1;
    mbar_wait(sb + SM_MBAR(jl % NST), (uint32_t)((jl / NST) & 1));
    TC_FENCE_AFTER();

    {
        const int sub = wid & 3;
        const int grp = wid >> 2;
        const int mg  = grp * 128 + sub * 32 + lid;
        float* dst = g_scratch + ((long)s * 256 + mg) * 512 + n0;
        #pragma unroll
        for (int c = 0; c < 8; c++) {
            uint32_t r[32];
            LDTM_X32(r, tb + (uint32_t)grp * 256u + (uint32_t)c * 32u);
            TC_WAIT_LD();
            #pragma unroll
            for (int q = 0; q < 8; q++) {
                *reinterpret_cast<float4*>(dst + c * 32 + q * 4) =
                    make_float4(__uint_as_float(r[q*4+0]), __uint_as_float(r[q*4+1]),
                                __uint_as_float(r[q*4+2]), __uint_as_float(r[q*4+3]));
            }
        }
    }

    __syncthreads();
    if (wid == 0) { TMEM_RELINQ(); TMEM_DEALLOC(tb, 512); }
#endif // HAS_TC
}

__global__ void reduce_k(float* __restrict__ out)
{
#if HAS_TC
    const int i = blockIdx.x * blockDim.x + threadIdx.x;
    const float4* sc = reinterpret_cast<const float4*>(g_scratch);
    float4 a = make_float4(0.f, 0.f, 0.f, 0.f);
    float4 b = make_float4(0.f, 0.f, 0.f, 0.f);
    #pragma unroll 4
    for (int s0 = 0; s0 < SPLITS; s0 += 2) {
        float4 u = sc[(long)s0 * 32768 + i];
        float4 v = sc[(long)(s0 + 1) * 32768 + i];
        a.x += u.x; a.y += u.y; a.z += u.z; a.w += u.w;
        b.x += v.x; b.y += v.y; b.z += v.z; b.w += v.w;
    }
    a.x += b.x; a.y += b.y; a.z += b.z; a.w += b.w;
    reinterpret_cast<float4*>(out)[i] = a;
#endif
}

extern "C" void kernel_launch(void* const* d_in, const int* in_sizes, int n_in,
                              void* d_out, int out_size)
{
    const float* x  = (const float*)d_in[0];   // (256, 640)
    const float* W  = (const float*)d_in[1];   // (128, 262656)
    const float* bv = (const float*)d_in[2];   // (262656,)
    float* out = (float*)d_out;                // (256, 512)

    cudaFuncSetAttribute(hyper_tc, cudaFuncAttributeMaxDynamicSharedMemorySize, SMEM_TOTAL);

    // Always-launched sequence; per-arch guards make exactly one path do work.
    zero_out_kernel<<<128, 256>>>(out);                         // out = 0 (needed by SIMT path)
    dim3 fgrid(2, 8, FSPLITS);
    hyper_main<<<fgrid, 256>>>(x, W, bv, out);                  // SIMT fallback (empty under TC)
    hyper_tc<<<dim3(2, SPLITS), 256, SMEM_TOTAL>>>(x, W, bv);   // tensor path (empty otherwise)
    reduce_k<<<128, 256>>>(out);                                // TC-only split merge
}

// round 5
// speedup vs baseline: 10.0350x; 1.1281x over previous
#include <cuda_runtime.h>
#include <cstdint>

// ---------------- arch-feature detection (proven working in R4) ----------------
#if defined(__CUDA_ARCH__) && (defined(__CUDA_ARCH_FEAT_SM103_ALL) || defined(__CUDA_ARCH_FEAT_SM100_ALL) || defined(__CUDA_ARCH_SPECIFIC__))
#define HAS_TC 1
#else
#define HAS_TC 0
#endif

#define NOISE   128
#define OUTF    512
#define XCOLS   640
#define WCOLS   262656
#define WB_OFF  262144

// chunk space: 2048 main (i0-outer, k-inner) + 16 feat-bias + 4 noise-bias + 1 const
#define CHUNKS  2069
#define SPLITS  74
#define CHPER   28
#define NST     3
#define NTHREADS 288       // warp 0 = MMA warp, warps 1-8 = 256 stagers

#define SM_A(st, mt) (1024u + ((st)*2u + (mt))*16384u)    // 6 x 16KB A tiles
#define SM_B(st)     (99328u + (st)*32768u)               // 3 x 32KB B tiles
#define SMEM_TOTAL   197632
#define SM_FULL(st)  (8u  + (st)*8u)
#define SM_EMPTY(st) (40u + (st)*8u)

// idesc: dtype F32(1)@[4], a/b TF32(2)@[7:9]/[10:12], N=256 -> 32@[17:22], M=128 -> 8@[24:28]
#define IDESC_TF32 ((1u<<4)|(2u<<7)|(2u<<10)|(32u<<17)|(8u<<24))

__device__ float g_scratch[(size_t)SPLITS * 256 * 512];   // split partials (38.8MB)

#if HAS_TC
// ---------------- PTX helpers ----------------
__device__ __forceinline__ uint32_t smem_u32(const void* p){
    uint32_t a;
    asm("{ .reg .u64 t; cvta.to.shared.u64 t, %1; cvt.u32.u64 %0, t; }" : "=r"(a) : "l"(p));
    return a;
}
__device__ __forceinline__ uint32_t sw128(uint32_t o){ return o ^ ((o >> 3) & 0x70u); }
__device__ __forceinline__ uint32_t f2tf32(float f){
    uint32_t r; asm("cvt.rna.tf32.f32 %0, %1;" : "=r"(r) : "f"(f)); return r;
}
__device__ __forceinline__ void sts128(uint32_t addr, uint32_t a, uint32_t b, uint32_t c, uint32_t d){
    asm volatile("st.shared.v4.b32 [%0], {%1,%2,%3,%4};"
                 :: "r"(addr), "r"(a), "r"(b), "r"(c), "r"(d) : "memory");
}
__device__ __forceinline__ bool elect1(){
    uint32_t p;
    asm volatile("{\n\t.reg .pred P;\n\telect.sync _|P, 0xFFFFFFFF;\n\tselp.b32 %0, 1, 0, P;\n\t}" : "=r"(p));
    return p != 0;
}
static constexpr unsigned long long DESC_BASE_SW128 =
    (2ull << 61) | (1ull << 46) | (64ull << 32) | (1ull << 16);
__device__ __forceinline__ uint64_t mkdesc(uint32_t addr){
    return DESC_BASE_SW128 | (uint64_t)((addr >> 4) & 0x3FFFu);
}
__device__ __forceinline__ void mma_tf32(uint32_t d, uint64_t ad, uint64_t bd, uint32_t en){
    asm volatile(
        "{\n\t.reg .pred p;\n\tsetp.ne.u32 p, %4, 0;\n\t"
        "tcgen05.mma.cta_group::1.kind::tf32 [%0], %1, %2, %3, {%5,%5,%5,%5}, p;\n\t}"
        :: "r"(d), "l"(ad), "l"(bd), "r"(IDESC_TF32), "r"(en), "r"(0u) : "memory");
}
#define TMEM_ALLOC(smem_addr, ncols) \
    asm volatile("tcgen05.alloc.cta_group::1.sync.aligned.shared::cta.b32 [%0], %1;" \
                 :: "r"(smem_addr), "r"((uint32_t)(ncols)) : "memory")
#define TMEM_DEALLOC(tmem, ncols) \
    asm volatile("tcgen05.dealloc.cta_group::1.sync.aligned.b32 %0, %1;" :: "r"(tmem), "r"((uint32_t)(ncols)))
#define TMEM_RELINQ() asm volatile("tcgen05.relinquish_alloc_permit.cta_group::1.sync.aligned;")
#define MBAR_INIT(a, n) \
    asm volatile("mbarrier.init.shared.b64 [%0], %1;" :: "r"(a), "r"((uint32_t)(n)) : "memory")
#define MBAR_ARRIVE(a) \
    asm volatile("mbarrier.arrive.shared.b64 _, [%0];" :: "r"(a) : "memory")
#define TC_COMMIT(a) \
    asm volatile("tcgen05.commit.cta_group::1.mbarrier::arrive::one.shared::cluster.b64 [%0];" :: "r"(a) : "memory")
#define FENCE_ASYNC() asm volatile("fence.proxy.async.shared::cta;" ::: "memory")
#define TC_FENCE_AFTER() asm volatile("tcgen05.fence::after_thread_sync;" ::: "memory")
#define TC_WAIT_LD() asm volatile("tcgen05.wait::ld.sync.aligned;" ::: "memory")

__device__ __forceinline__ void mbar_wait(uint32_t mbar, uint32_t parity){
    uint32_t done;
    asm volatile(
        "{\n\t.reg .pred p;\n\t"
        "mbarrier.try_wait.parity.acquire.cta.shared::cta.b64 p, [%1], %2;\n\t"
        "selp.b32 %0, 1, 0, p;\n\t}"
        : "=r"(done) : "r"(mbar), "r"(parity) : "memory");
    if (!done) {
        asm volatile(
            "{\n\t.reg .pred P1;\n\t"
            "WL_%=:\n\t"
            "mbarrier.try_wait.parity.acquire.cta.shared::cta.b64 P1, [%0], %1, 0x989680;\n\t"
            "@P1 bra.uni WD_%=;\n\t"
            "bra.uni WL_%=;\n\t"
            "WD_%=:\n\t}"
            :: "r"(mbar), "r"(parity) : "memory");
    }
}
#define LDTM_X32(r, a) \
    asm volatile("tcgen05.ld.sync.aligned.32x32b.x32.b32 " \
        "{%0,%1,%2,%3,%4,%5,%6,%7,%8,%9,%10,%11,%12,%13,%14,%15," \
        "%16,%17,%18,%19,%20,%21,%22,%23,%24,%25,%26,%27,%28,%29,%30,%31}, [%32];" \
        : "=r"((r)[0]),"=r"((r)[1]),"=r"((r)[2]),"=r"((r)[3]),"=r"((r)[4]),"=r"((r)[5]),"=r"((r)[6]),"=r"((r)[7]), \
          "=r"((r)[8]),"=r"((r)[9]),"=r"((r)[10]),"=r"((r)[11]),"=r"((r)[12]),"=r"((r)[13]),"=r"((r)[14]),"=r"((r)[15]), \
          "=r"((r)[16]),"=r"((r)[17]),"=r"((r)[18]),"=r"((r)[19]),"=r"((r)[20]),"=r"((r)[21]),"=r"((r)[22]),"=r"((r)[23]), \
          "=r"((r)[24]),"=r"((r)[25]),"=r"((r)[26]),"=r"((r)[27]),"=r"((r)[28]),"=r"((r)[29]),"=r"((r)[30]),"=r"((r)[31]) \
        : "r"(a))
#endif // HAS_TC

__global__ __launch_bounds__(NTHREADS, 1)
void hyper_tc(const float* __restrict__ x, const float* __restrict__ W,
              const float* __restrict__ bv)
{
#if HAS_TC
    extern __shared__ char smem[];
    const uint32_t sb  = smem_u32(smem);
    const int tid = threadIdx.x;
    const int wid = tid >> 5;
    const int lid = tid & 31;
    const int nt  = blockIdx.x;              // 0..1 : n-tile
    const int s   = blockIdx.y;              // 0..73: K-split
    const int n0  = nt * 256;
    const int c0  = s * CHPER;
    const int c1  = min(CHUNKS, c0 + CHPER);
    const int nCh = c1 - c0;

    if (wid == 0) TMEM_ALLOC(sb, 512);
    if (tid == 0) {
        #pragma unroll
        for (int st = 0; st < NST; st++) {
            MBAR_INIT(sb + SM_FULL(st), 256);   // 256 stager arrivals
            MBAR_INIT(sb + SM_EMPTY(st), 1);    // tcgen05.commit
        }
    }
    __syncthreads();
    uint32_t tb;
    asm volatile("ld.shared.b32 %0, [%1];" : "=r"(tb) : "r"(sb));

    if (wid == 0) {
        // ================= MMA warp =================
        for (int j = 0; j < nCh; j++) {
            const int st = j % NST;
            mbar_wait(sb + SM_FULL(st), (uint32_t)((j / NST) & 1));
            if (elect1()) {
                uint64_t ad0 = mkdesc(sb + SM_A(st, 0));
                uint64_t ad1 = mkdesc(sb + SM_A(st, 1));
                uint64_t bd  = mkdesc(sb + SM_B(st));
                #pragma unroll
                for (int ks = 0; ks < 4; ks++) {
                    uint32_t en = (j == 0 && ks == 0) ? 0u : 1u;
                    mma_tf32(tb,        ad0 + ks * 2, bd + ks * 2, en);
                    mma_tf32(tb + 256u, ad1 + ks * 2, bd + ks * 2, en);
                }
                TC_COMMIT(sb + SM_EMPTY(st));
            }
        }
    } else {
        // ================= stager threads: u in [0,256) =================
        const int u = tid - 32;                  // B row n = u; A row: mt = u>>7, m = u&127; x row = u
        const float* xg = x + (long)u * XCOLS;
        const uint32_t mt  = (uint32_t)(u >> 7);
        const uint32_t m   = (uint32_t)(u & 127);
        const uint32_t arow = m * 128u;          // A tile row byte offset
        const uint32_t brow = (uint32_t)u * 128u;

        float fa[32];
        int   akey_cur = -2;

        for (int j = 0; j < nCh; j++) {
            const int c  = c0 + j;
            const int st = j % NST;

            // ---- decode chunk ----
            const float* bp; long bstr; float nv; int akey; int case3 = 0;
            if (c < 2048) {                      // main: i0-outer, k-inner
                int i0 = (c >> 7) << 5;
                int k  = c & 127;
                bp = W + (long)k * WCOLS + (long)i0 * OUTF + n0 + u; bstr = OUTF;
                nv = xg[k];
                akey = NOISE + i0;
            } else if (c < 2064) {               // feats @ bias-weight
                int i0 = (c - 2048) << 5;
                bp = bv + (long)i0 * OUTF + n0 + u; bstr = OUTF;
                nv = 1.f;
                akey = NOISE + i0;
            } else if (c < 2068) {               // noise @ W-bias
                int k0 = (c - 2064) << 5;
                bp = W + (long)k0 * WCOLS + WB_OFF + n0 + u; bstr = WCOLS;
                nv = 1.f;
                akey = k0;
            } else {                             // const bias
                bp = bv + WB_OFF + n0 + u; bstr = 0;
                nv = 0.f; akey = -1; case3 = 1;
            }

            // ---- issue LDGs before the empty-wait (overlap wait with memory) ----
            if (akey >= 0 && akey != akey_cur) {
                #pragma unroll
                for (int q = 0; q < 8; q++) {
                    float4 f = *reinterpret_cast<const float4*>(xg + akey + q * 4);
                    fa[q*4+0] = f.x; fa[q*4+1] = f.y; fa[q*4+2] = f.z; fa[q*4+3] = f.w;
                }
                akey_cur = akey;
            }
            float br[32];
            #pragma unroll
            for (int kk = 0; kk < 32; kk++) br[kk] = bp[(long)kk * bstr];

            // ---- wait for stage buffers free ----
            if (j >= NST) mbar_wait(sb + SM_EMPTY(st), (uint32_t)(((j / NST) - 1) & 1));

            // ---- stage B row (8 STS.128) ----
            {
                uint32_t bb = sb + SM_B(st);
                #pragma unroll
                for (int q = 0; q < 8; q++) {
                    uint32_t off = brow + (uint32_t)q * 16u;
                    sts128(bb + sw128(off),
                           f2tf32(br[q*4+0]), f2tf32(br[q*4+1]),
                           f2tf32(br[q*4+2]), f2tf32(br[q*4+3]));
                }
            }
            // ---- stage A row (8 STS.128) ----
            {
                uint32_t ab = sb + SM_A(st, mt);
                #pragma unroll
                for (int q = 0; q < 8; q++) {
                    float v0, v1, v2, v3;
                    if (case3) {
                        v0 = (q == 0) ? 1.f : 0.f; v1 = 0.f; v2 = 0.f; v3 = 0.f;
                    } else {
                        v0 = nv * fa[q*4+0]; v1 = nv * fa[q*4+1];
                        v2 = nv * fa[q*4+2]; v3 = nv * fa[q*4+3];
                    }
                    uint32_t off = arow + (uint32_t)q * 16u;
                    sts128(ab + sw128(off), f2tf32(v0), f2tf32(v1), f2tf32(v2), f2tf32(v3));
                }
            }
            FENCE_ASYNC();
            MBAR_ARRIVE(sb + SM_FULL(st));
        }
    }

    // ---- all threads wait for final MMA completion ----
    const int jl = nCh - 1;
    mbar_wait(sb + SM_EMPTY(jl % NST), (uint32_t)((jl / NST) & 1));
    TC_FENCE_AFTER();
    __syncthreads();

    // ---- epilogue: warps 0-7 read TMEM, write split partials ----
    if (wid < 8) {
        const int sub = wid & 3;
        const int grp = wid >> 2;                 // m-tile
        const int mg  = grp * 128 + sub * 32 + lid;
        float* dst = g_scratch + ((long)s * 256 + mg) * 512 + n0;
        #pragma unroll
        for (int c = 0; c < 8; c++) {
            uint32_t r[32];
            LDTM_X32(r, tb + (uint32_t)grp * 256u + (uint32_t)c * 32u);
            TC_WAIT_LD();
            #pragma unroll
            for (int q = 0; q < 8; q++) {
                *reinterpret_cast<float4*>(dst + c * 32 + q * 4) =
                    make_float4(__uint_as_float(r[q*4+0]), __uint_as_float(r[q*4+1]),
                                __uint_as_float(r[q*4+2]), __uint_as_float(r[q*4+3]));
            }
        }
    }

    __syncthreads();
    if (wid == 0) { TMEM_RELINQ(); TMEM_DEALLOC(tb, 512); }
#endif // HAS_TC
}

// ---------------- split reduction: 65536 float2 outputs, 512 blocks ----------------
__global__ void reduce_k(float* __restrict__ out)
{
    const int g = blockIdx.x * blockDim.x + threadIdx.x;     // 0..65535
    const float2* sc = reinterpret_cast<const float2*>(g_scratch);
    float2 a = make_float2(0.f, 0.f);
    float2 b = make_float2(0.f, 0.f);
    #pragma unroll 4
    for (int t = 0; t < SPLITS / 2; t++) {
        float2 u = sc[(size_t)t * 65536 + g];
        float2 v = sc[(size_t)(t + SPLITS / 2) * 65536 + g];
        a.x += u.x; a.y += u.y;
        b.x += v.x; b.y += v.y;
    }
    reinterpret_cast<float2*>(out)[g] = make_float2(a.x + b.x, a.y + b.y);
}

extern "C" void kernel_launch(void* const* d_in, const int* in_sizes, int n_in,
                              void* d_out, int out_size)
{
    const float* x  = (const float*)d_in[0];   // (256, 640)
    const float* W  = (const float*)d_in[1];   // (128, 262656)
    const float* bv = (const float*)d_in[2];   // (262656,)
    float* out = (float*)d_out;                // (256, 512)

    cudaFuncSetAttribute(hyper_tc, cudaFuncAttributeMaxDynamicSharedMemorySize, SMEM_TOTAL);
    hyper_tc<<<dim3(2, SPLITS), NTHREADS, SMEM_TOTAL>>>(x, W, bv);
    reduce_k<<<512, 128>>>(out);
}